// round 2
// baseline (speedup 1.0000x reference)
#include <cuda_runtime.h>
#include <cuda_bf16.h>
#include <math.h>

#define SQ 2048      // S
#define DM 2048      // D
#define LL 4096      // 2*S
#define NH 32        // heads
#define HDM 64       // head dim
#define FFD 8192     // FF
#define LN_EPS 1e-5f

// ---------------- scratch (device globals; allocation-free) ----------------
__device__ float g_x[(size_t)LL * DM];      // concat(ln(mem), ln(hidden))
__device__ float g_q[(size_t)LL * DM];
__device__ float g_k[(size_t)LL * DM];
__device__ float g_v[(size_t)LL * DM];
__device__ float g_attn[(size_t)SQ * DM];   // attention output (pre-Wo)
__device__ float g_h[(size_t)SQ * DM];      // residual + attn @ Wo^T
__device__ float g_h2[(size_t)SQ * DM];     // ln2(g_h)
__device__ float g_gate[(size_t)SQ * FFD];
__device__ float g_up[(size_t)SQ * FFD];

// ---------------- warp reduce helpers ----------------
__device__ __forceinline__ float warp_sum(float v) {
    #pragma unroll
    for (int o = 16; o > 0; o >>= 1) v += __shfl_xor_sync(0xffffffffu, v, o);
    return v;
}
__device__ __forceinline__ float warp_max(float v) {
    #pragma unroll
    for (int o = 16; o > 0; o >>= 1) v = fmaxf(v, __shfl_xor_sync(0xffffffffu, v, o));
    return v;
}

// ---------------- LayerNorm: one block per row of DM ----------------
__global__ void ln_kernel(const float* __restrict__ in, float* __restrict__ out,
                          const float* __restrict__ w, const float* __restrict__ b) {
    int row = blockIdx.x;
    const float* x = in + (size_t)row * DM;
    float* y = out + (size_t)row * DM;
    int tid = threadIdx.x;

    float s = 0.f, s2 = 0.f;
    for (int i = tid; i < DM; i += 256) {
        float v = x[i];
        s += v; s2 += v * v;
    }
    __shared__ float rs[8], rs2[8];
    float ws = warp_sum(s), ws2 = warp_sum(s2);
    int wid = tid >> 5, lane = tid & 31;
    if (lane == 0) { rs[wid] = ws; rs2[wid] = ws2; }
    __syncthreads();
    float ts = 0.f, ts2 = 0.f;
    #pragma unroll
    for (int i = 0; i < 8; i++) { ts += rs[i]; ts2 += rs2[i]; }
    float mean = ts * (1.0f / DM);
    float var  = ts2 * (1.0f / DM) - mean * mean;
    float inv  = rsqrtf(var + LN_EPS);
    for (int i = tid; i < DM; i += 256) {
        y[i] = (x[i] - mean) * inv * w[i] + b[i];
    }
}

// ---------------- SGEMM: C[M,N] = A[M,K] @ B[N,K]^T (+R) ----------------
#define BM 128
#define BN 128
#define BK 8
__global__ void __launch_bounds__(256, 2)
gemm_nt(const float* __restrict__ A, const float* __restrict__ B,
        const float* __restrict__ R, float* __restrict__ C,
        int M, int N, int K) {
    __shared__ __align__(16) float As[BK][BM];
    __shared__ __align__(16) float Bs[BK][BN];

    int bm = blockIdx.y * BM;
    int bn = blockIdx.x * BN;
    int tid = threadIdx.x;
    int tx = tid & 15;       // 0..15 -> N
    int ty = tid >> 4;       // 0..15 -> M

    int arow = tid >> 1;          // 0..127
    int acol = (tid & 1) * 4;     // 0 or 4
    const float* Aptr = A + (size_t)(bm + arow) * K + acol;
    const float* Bptr = B + (size_t)(bn + arow) * K + acol;

    float acc[8][8];
    #pragma unroll
    for (int i = 0; i < 8; i++)
        #pragma unroll
        for (int j = 0; j < 8; j++) acc[i][j] = 0.f;

    for (int k0 = 0; k0 < K; k0 += BK) {
        float4 a4 = *(const float4*)(Aptr + k0);
        float4 b4 = *(const float4*)(Bptr + k0);
        __syncthreads();
        As[acol + 0][arow] = a4.x; As[acol + 1][arow] = a4.y;
        As[acol + 2][arow] = a4.z; As[acol + 3][arow] = a4.w;
        Bs[acol + 0][arow] = b4.x; Bs[acol + 1][arow] = b4.y;
        Bs[acol + 2][arow] = b4.z; Bs[acol + 3][arow] = b4.w;
        __syncthreads();
        #pragma unroll
        for (int kk = 0; kk < BK; kk++) {
            float af[8], bf[8];
            *(float4*)(af)     = *(const float4*)(&As[kk][ty * 8]);
            *(float4*)(af + 4) = *(const float4*)(&As[kk][ty * 8 + 4]);
            *(float4*)(bf)     = *(const float4*)(&Bs[kk][tx * 8]);
            *(float4*)(bf + 4) = *(const float4*)(&Bs[kk][tx * 8 + 4]);
            #pragma unroll
            for (int i = 0; i < 8; i++)
                #pragma unroll
                for (int j = 0; j < 8; j++)
                    acc[i][j] += af[i] * bf[j];
        }
    }

    #pragma unroll
    for (int i = 0; i < 8; i++) {
        int m = bm + ty * 8 + i;
        float* crow = C + (size_t)m * N + bn + tx * 8;
        const float* rrow = R ? (R + (size_t)m * N + bn + tx * 8) : nullptr;
        #pragma unroll
        for (int j = 0; j < 8; j += 4) {
            float4 val;
            val.x = acc[i][j];     val.y = acc[i][j + 1];
            val.z = acc[i][j + 2]; val.w = acc[i][j + 3];
            if (rrow) {
                float4 r4 = *(const float4*)(rrow + j);
                val.x += r4.x; val.y += r4.y; val.z += r4.z; val.w += r4.w;
            }
            *(float4*)(crow + j) = val;
        }
    }
}

// ---------------- RoPE: first 16 dims of each head, pairs (j, j+8) ----------
__global__ void rope_kernel(float* __restrict__ q, float* __restrict__ k,
                            const int* __restrict__ pos_ids) {
    int idx = blockIdx.x * blockDim.x + threadIdx.x;   // (l, h, j)
    int j = idx & 7;
    int h = (idx >> 3) & 31;
    int l = idx >> 8;
    if (l >= LL) return;
    int pos = pos_ids[l & (SQ - 1)];
    // inv_freq = 10000^(-j/8) = exp(-j * ln(10000)/8)
    float inv_freq = __expf(-(float)j * 1.1512925464970230f);
    float ang = (float)pos * inv_freq;
    float c, s;
    __sincosf(ang, &s, &c);
    // full precision trig for safety
    c = cosf(ang); s = sinf(ang);

    size_t base = (size_t)l * DM + h * HDM;
    float q1 = q[base + j], q2 = q[base + j + 8];
    q[base + j]     = q1 * c - q2 * s;
    q[base + j + 8] = q2 * c + q1 * s;
    float k1 = k[base + j], k2 = k[base + j + 8];
    k[base + j]     = k1 * c - k2 * s;
    k[base + j + 8] = k2 * c + k1 * s;
}

// ---------------- Attention ----------------
// Query i (hidden row S+i) attends: memory keys j < i, plus self key row S+i.
// One warp per query, 8 warps/block, K/V chunks of 32 staged in SMEM.
__global__ void __launch_bounds__(256)
attn_kernel(const float* __restrict__ q, const float* __restrict__ k,
            const float* __restrict__ v, float* __restrict__ out) {
    int h = blockIdx.y;
    int tid = threadIdx.x;
    int warp = tid >> 5, lane = tid & 31;
    int i = blockIdx.x * 8 + warp;          // query index 0..SQ-1

    __shared__ float qs[8][HDM];
    __shared__ float ks[32][HDM + 1];
    __shared__ float vs[32][HDM + 2];

    // load 8 query rows (hidden half: rows S+i)
    for (int idx = tid; idx < 8 * HDM; idx += 256) {
        int r = idx >> 6, c = idx & 63;
        qs[r][c] = q[(size_t)(SQ + blockIdx.x * 8 + r) * DM + h * HDM + c];
    }
    __syncthreads();

    float m = -INFINITY, lsum = 0.f, acc0 = 0.f, acc1 = 0.f;

    int i_max = blockIdx.x * 8 + 7;
    int nch = (i_max + 31) >> 5;            // chunks covering keys < i_max
    for (int ch = 0; ch < nch; ch++) {
        int j0 = ch << 5;
        __syncthreads();
        for (int idx = tid; idx < 32 * HDM; idx += 256) {
            int r = idx >> 6, c = idx & 63;
            size_t off = (size_t)(j0 + r) * DM + h * HDM + c;
            ks[r][c] = k[off];
            vs[r][c] = v[off];
        }
        __syncthreads();

        if (j0 < i) {   // warp-uniform
            int j = j0 + lane;
            float s_t = 0.f;
            #pragma unroll
            for (int d = 0; d < HDM; d++) s_t += qs[warp][d] * ks[lane][d];
            s_t *= 0.125f;
            if (j >= i) s_t = -INFINITY;

            float mx = warp_max(s_t);
            float m_new = fmaxf(m, mx);
            float scale = __expf(m - m_new);     // exp(-inf)=0 on first chunk
            float p = __expf(s_t - m_new);
            lsum = lsum * scale + warp_sum(p);
            acc0 *= scale; acc1 *= scale;
            #pragma unroll
            for (int t = 0; t < 32; t++) {
                float pt = __shfl_sync(0xffffffffu, p, t);
                acc0 += pt * vs[t][2 * lane];
                acc1 += pt * vs[t][2 * lane + 1];
            }
            m = m_new;
        }
    }

    // self key: row S+i
    {
        const float* kself = k + (size_t)(SQ + i) * DM + h * HDM;
        const float* vself = v + (size_t)(SQ + i) * DM + h * HDM;
        float part = qs[warp][2 * lane] * kself[2 * lane]
                   + qs[warp][2 * lane + 1] * kself[2 * lane + 1];
        float s_self = warp_sum(part) * 0.125f;
        float m_new = fmaxf(m, s_self);
        float scale = __expf(m - m_new);
        float pself = __expf(s_self - m_new);
        lsum = lsum * scale + pself;
        acc0 = acc0 * scale + pself * vself[2 * lane];
        acc1 = acc1 * scale + pself * vself[2 * lane + 1];
    }

    float invl = 1.0f / lsum;
    size_t ob = (size_t)i * DM + h * HDM;
    out[ob + 2 * lane]     = acc0 * invl;
    out[ob + 2 * lane + 1] = acc1 * invl;
}

// ---------------- SiLU(gate) * up (in-place into gate) ----------------
__global__ void silu_mul_kernel(float* __restrict__ gate, const float* __restrict__ up) {
    size_t i = (size_t)blockIdx.x * blockDim.x + threadIdx.x;
    if (i < (size_t)SQ * FFD) {
        float g = gate[i];
        gate[i] = g / (1.0f + __expf(-g)) * up[i];
    }
}

// ---------------- launch ----------------
extern "C" void kernel_launch(void* const* d_in, const int* in_sizes, int n_in,
                              void* d_out, int out_size) {
    const float* hidden = (const float*)d_in[0];
    const float* memory = (const float*)d_in[1];
    // d_in[2] attention_mask: causal; structure implemented directly
    const int*   pos    = (const int*)d_in[3];
    const float* ln1w   = (const float*)d_in[4];
    const float* ln1b   = (const float*)d_in[5];
    const float* ln2w   = (const float*)d_in[6];
    const float* ln2b   = (const float*)d_in[7];
    const float* Wq     = (const float*)d_in[8];
    const float* Wk     = (const float*)d_in[9];
    const float* Wv     = (const float*)d_in[10];
    const float* Wo     = (const float*)d_in[11];
    const float* Wg     = (const float*)d_in[12];
    const float* Wu     = (const float*)d_in[13];
    const float* Wd     = (const float*)d_in[14];
    float* out = (float*)d_out;

    float *x, *q, *k, *v, *attn, *h, *h2, *gate, *up;
    cudaGetSymbolAddress((void**)&x,    g_x);
    cudaGetSymbolAddress((void**)&q,    g_q);
    cudaGetSymbolAddress((void**)&k,    g_k);
    cudaGetSymbolAddress((void**)&v,    g_v);
    cudaGetSymbolAddress((void**)&attn, g_attn);
    cudaGetSymbolAddress((void**)&h,    g_h);
    cudaGetSymbolAddress((void**)&h2,   g_h2);
    cudaGetSymbolAddress((void**)&gate, g_gate);
    cudaGetSymbolAddress((void**)&up,   g_up);

    // LN1: x = concat(ln(memory), ln(hidden))
    ln_kernel<<<SQ, 256>>>(memory, x, ln1w, ln1b);
    ln_kernel<<<SQ, 256>>>(hidden, x + (size_t)SQ * DM, ln1w, ln1b);

    // QKV projections over all L=4096 tokens
    dim3 g_qkv(DM / BN, LL / BM);
    gemm_nt<<<g_qkv, 256>>>(x, Wq, nullptr, q, LL, DM, DM);
    gemm_nt<<<g_qkv, 256>>>(x, Wk, nullptr, k, LL, DM, DM);
    gemm_nt<<<g_qkv, 256>>>(x, Wv, nullptr, v, LL, DM, DM);

    // RoPE on first 16 dims of every head (q and k)
    rope_kernel<<<(LL * NH * 8) / 256, 256>>>(q, k, pos);

    // Attention (hidden queries only)
    attn_kernel<<<dim3(SQ / 8, NH), 256>>>(q, k, v, attn);

    // Wo + residual(hidden)
    gemm_nt<<<dim3(DM / BN, SQ / BM), 256>>>(attn, Wo, hidden, h, SQ, DM, DM);

    // LN2
    ln_kernel<<<SQ, 256>>>(h, h2, ln2w, ln2b);

    // MLP
    dim3 g_ff(FFD / BN, SQ / BM);
    gemm_nt<<<g_ff, 256>>>(h2, Wg, nullptr, gate, SQ, FFD, DM);
    gemm_nt<<<g_ff, 256>>>(h2, Wu, nullptr, up,   SQ, FFD, DM);
    silu_mul_kernel<<<(SQ * FFD) / 256, 256>>>(gate, up);

    // Wd + residual(h) -> output
    gemm_nt<<<dim3(DM / BN, SQ / BM), 256>>>(gate, Wd, h, out, SQ, DM, FFD);
}

// round 4
// speedup vs baseline: 2.1355x; 2.1355x over previous
#include <cuda_runtime.h>
#include <cuda_bf16.h>
#include <math.h>
#include <stdint.h>

#define SQ 2048      // S
#define DM 2048      // D
#define LL 4096      // 2*S
#define NH 32        // heads
#define HDM 64       // head dim
#define FFD 8192     // FF
#define LN_EPS 1e-5f

// ---------------- fp32 scratch ----------------
__device__ float g_x[(size_t)LL * DM];
__device__ float g_q[(size_t)LL * DM];
__device__ float g_k[(size_t)LL * DM];
__device__ float g_v[(size_t)LL * DM];
__device__ float g_attn[(size_t)SQ * DM];
__device__ float g_h[(size_t)SQ * DM];
__device__ float g_h2[(size_t)SQ * DM];
__device__ float g_gate[(size_t)SQ * FFD];
__device__ float g_up[(size_t)SQ * FFD];

// ---------------- bf16 split (hi/lo) scratch ----------------
__device__ __nv_bfloat16 g_xh[(size_t)LL * DM],  g_xl[(size_t)LL * DM];
__device__ __nv_bfloat16 g_ath[(size_t)SQ * DM], g_atl[(size_t)SQ * DM];
__device__ __nv_bfloat16 g_h2h[(size_t)SQ * DM], g_h2l[(size_t)SQ * DM];
__device__ __nv_bfloat16 g_gth[(size_t)SQ * FFD], g_gtl[(size_t)SQ * FFD];
__device__ __nv_bfloat16 g_wqh[(size_t)DM * DM], g_wql[(size_t)DM * DM];
__device__ __nv_bfloat16 g_wkh[(size_t)DM * DM], g_wkl[(size_t)DM * DM];
__device__ __nv_bfloat16 g_wvh[(size_t)DM * DM], g_wvl[(size_t)DM * DM];
__device__ __nv_bfloat16 g_woh[(size_t)DM * DM], g_wol[(size_t)DM * DM];
__device__ __nv_bfloat16 g_wgh[(size_t)FFD * DM], g_wgl[(size_t)FFD * DM];
__device__ __nv_bfloat16 g_wuh[(size_t)FFD * DM], g_wul[(size_t)FFD * DM];
__device__ __nv_bfloat16 g_wdh[(size_t)DM * FFD], g_wdl[(size_t)DM * FFD];

// ---------------- PTX helpers ----------------
__device__ __forceinline__ uint32_t smem_u32(const void* p) {
    uint32_t a;
    asm("{ .reg .u64 t; cvta.to.shared.u64 t, %1; cvt.u32.u64 %0, t; }" : "=r"(a) : "l"(p));
    return a;
}
__device__ __forceinline__ void cp_async16(uint32_t dst, const void* src) {
    asm volatile("cp.async.cg.shared.global [%0], [%1], 16;" :: "r"(dst), "l"(src));
}
#define CP_COMMIT()  asm volatile("cp.async.commit_group;" ::: "memory")
#define CP_WAIT_1()  asm volatile("cp.async.wait_group 1;" ::: "memory")
#define CP_WAIT_0()  asm volatile("cp.async.wait_group 0;" ::: "memory")

__device__ __forceinline__ void ldsm_x4(uint32_t* r, uint32_t addr) {
    asm volatile("ldmatrix.sync.aligned.m8n8.x4.shared.b16 {%0,%1,%2,%3}, [%4];"
                 : "=r"(r[0]), "=r"(r[1]), "=r"(r[2]), "=r"(r[3]) : "r"(addr));
}
__device__ __forceinline__ void ldsm_x2(uint32_t* r, uint32_t addr) {
    asm volatile("ldmatrix.sync.aligned.m8n8.x2.shared.b16 {%0,%1}, [%2];"
                 : "=r"(r[0]), "=r"(r[1]) : "r"(addr));
}
__device__ __forceinline__ void mma_bf16(float* c, const uint32_t* a, const uint32_t* b) {
    asm volatile(
        "mma.sync.aligned.m16n8k16.row.col.f32.bf16.bf16.f32 "
        "{%0,%1,%2,%3}, {%4,%5,%6,%7}, {%8,%9}, {%0,%1,%2,%3};"
        : "+f"(c[0]), "+f"(c[1]), "+f"(c[2]), "+f"(c[3])
        : "r"(a[0]), "r"(a[1]), "r"(a[2]), "r"(a[3]), "r"(b[0]), "r"(b[1]));
}

// ---------------- tile geometry ----------------
#define BMH 128
#define BNH 128
#define BKH 32
#define NSTAGE 3
#define STAGE_BYTES 16384            // A 8KB + B 8KB
#define SMEM_BYTES (NSTAGE * STAGE_BYTES)

// smem swizzle: 64B rows of BK=32 bf16; 16B chunk index XOR ((row>>1)&3)
__device__ __forceinline__ uint32_t sw_off(int row, int c4) {
    return (uint32_t)(row * 64 + ((c4 ^ ((row >> 1) & 3)) << 4));
}

// ---------------- split-bf16 HMMA GEMM: C[M,N] = A@B^T (+R) ----------------
// A,B given as hi/lo bf16 pairs; 3 passes: Ah*Bh + Ah*Bl + Al*Bh (fp32 acc).
__global__ void __launch_bounds__(256, 2)
gemm_hmma(const __nv_bfloat16* __restrict__ Ah, const __nv_bfloat16* __restrict__ Al,
          const __nv_bfloat16* __restrict__ Bh, const __nv_bfloat16* __restrict__ Bl,
          const float* __restrict__ R, float* __restrict__ C,
          int M, int N, int K) {
    extern __shared__ __align__(128) char smem[];
    uint32_t sbase = smem_u32(smem);
    int tid = threadIdx.x, lane = tid & 31, wid = tid >> 5;
    int bm = blockIdx.y * BMH, bn = blockIdx.x * BNH;
    int warp_m = wid & 1, warp_n = wid >> 1;         // 2 x 4 warp grid
    int m_base = warp_m * 64, n_base = warp_n * 32;

    int kchunks = K / BKH;
    int nch = kchunks * 3;

    float acc[4][4][4];
    #pragma unroll
    for (int i = 0; i < 4; i++)
        #pragma unroll
        for (int j = 0; j < 4; j++)
            #pragma unroll
            for (int t = 0; t < 4; t++) acc[i][j][t] = 0.f;

    // loader precompute: each thread handles rows (tid>>2) and (tid>>2)+64, chunk tid&3
    int lrow = tid >> 2, lc4 = tid & 3;
    uint32_t dA0 = sw_off(lrow, lc4),       dA1 = sw_off(lrow + 64, lc4);
    size_t goffA0 = (size_t)(bm + lrow) * K + lc4 * 8;
    size_t goffA1 = (size_t)(bm + lrow + 64) * K + lc4 * 8;
    size_t goffB0 = (size_t)(bn + lrow) * K + lc4 * 8;
    size_t goffB1 = (size_t)(bn + lrow + 64) * K + lc4 * 8;

    auto load_chunk = [&](int c) {
        int pass = c / kchunks;
        int k0 = (c - pass * kchunks) * BKH;
        const __nv_bfloat16* Ap = (pass == 2) ? Al : Ah;
        const __nv_bfloat16* Bp = (pass == 1) ? Bl : Bh;
        uint32_t st = sbase + (c % NSTAGE) * STAGE_BYTES;
        cp_async16(st + dA0,        Ap + goffA0 + k0);
        cp_async16(st + dA1,        Ap + goffA1 + k0);
        cp_async16(st + 8192 + dA0, Bp + goffB0 + k0);
        cp_async16(st + 8192 + dA1, Bp + goffB1 + k0);
        CP_COMMIT();
    };

    load_chunk(0);
    load_chunk(1);

    // ldmatrix address precompute (row-dependent parts)
    int ar = lane & 15;          // A row within m16 tile
    int ac = lane >> 4;          // A 16B chunk select (k half)
    int br = lane & 7;           // B row within n8 tile
    int bc = (lane >> 3) & 1;    // B 16B chunk select

    for (int c = 0; c < nch; c++) {
        if (c < nch - 1) { CP_WAIT_1(); } else { CP_WAIT_0(); }
        __syncthreads();

        uint32_t sA = sbase + (c % NSTAGE) * STAGE_BYTES;
        uint32_t sB = sA + 8192;

        #pragma unroll
        for (int ks = 0; ks < 2; ks++) {
            uint32_t afr[4][4], bfr[4][2];
            #pragma unroll
            for (int mi = 0; mi < 4; mi++) {
                int row = m_base + mi * 16 + ar;
                ldsm_x4(afr[mi], sA + sw_off(row, ks * 2 + ac));
            }
            #pragma unroll
            for (int nj = 0; nj < 4; nj++) {
                int row = n_base + nj * 8 + br;
                ldsm_x2(bfr[nj], sB + sw_off(row, ks * 2 + bc));
            }
            #pragma unroll
            for (int mi = 0; mi < 4; mi++)
                #pragma unroll
                for (int nj = 0; nj < 4; nj++)
                    mma_bf16(acc[mi][nj], afr[mi], bfr[nj]);
        }

        if (c + 2 < nch) load_chunk(c + 2);
    }

    // epilogue
    int er = lane >> 2;              // 0..7
    int ec = (lane & 3) * 2;
    #pragma unroll
    for (int mi = 0; mi < 4; mi++) {
        #pragma unroll
        for (int half = 0; half < 2; half++) {
            int row = bm + m_base + mi * 16 + half * 8 + er;
            float* cp = C + (size_t)row * N + bn + n_base + ec;
            const float* rp = R ? (R + (size_t)row * N + bn + n_base + ec) : nullptr;
            #pragma unroll
            for (int nj = 0; nj < 4; nj++) {
                float2 v;
                v.x = acc[mi][nj][half * 2];
                v.y = acc[mi][nj][half * 2 + 1];
                if (rp) {
                    float2 r2 = *(const float2*)(rp + nj * 8);
                    v.x += r2.x; v.y += r2.y;
                }
                *(float2*)(cp + nj * 8) = v;
            }
        }
    }
}

// ---------------- split fp32 -> bf16 hi/lo ----------------
__global__ void split_kernel(const float* __restrict__ in,
                             __nv_bfloat16* __restrict__ hi,
                             __nv_bfloat16* __restrict__ lo, int n4) {
    int i = blockIdx.x * 256 + threadIdx.x;
    if (i >= n4) return;
    float4 v = ((const float4*)in)[i];
    __nv_bfloat16 h0 = __float2bfloat16(v.x), h1 = __float2bfloat16(v.y);
    __nv_bfloat16 h2 = __float2bfloat16(v.z), h3 = __float2bfloat16(v.w);
    __nv_bfloat16 l0 = __float2bfloat16(v.x - __bfloat162float(h0));
    __nv_bfloat16 l1 = __float2bfloat16(v.y - __bfloat162float(h1));
    __nv_bfloat16 l2 = __float2bfloat16(v.z - __bfloat162float(h2));
    __nv_bfloat16 l3 = __float2bfloat16(v.w - __bfloat162float(h3));
    __nv_bfloat162* hp = (__nv_bfloat162*)hi;
    __nv_bfloat162* lp = (__nv_bfloat162*)lo;
    hp[2 * i]     = __nv_bfloat162(h0, h1);
    hp[2 * i + 1] = __nv_bfloat162(h2, h3);
    lp[2 * i]     = __nv_bfloat162(l0, l1);
    lp[2 * i + 1] = __nv_bfloat162(l2, l3);
}

// ---------------- warp reduce ----------------
__device__ __forceinline__ float warp_sum(float v) {
    #pragma unroll
    for (int o = 16; o > 0; o >>= 1) v += __shfl_xor_sync(0xffffffffu, v, o);
    return v;
}
__device__ __forceinline__ float warp_max(float v) {
    #pragma unroll
    for (int o = 16; o > 0; o >>= 1) v = fmaxf(v, __shfl_xor_sync(0xffffffffu, v, o));
    return v;
}

// ---------------- LayerNorm ----------------
__global__ void ln_kernel(const float* __restrict__ in, float* __restrict__ out,
                          const float* __restrict__ w, const float* __restrict__ b) {
    int row = blockIdx.x;
    const float* x = in + (size_t)row * DM;
    float* y = out + (size_t)row * DM;
    int tid = threadIdx.x;
    float s = 0.f, s2 = 0.f;
    for (int i = tid; i < DM; i += 256) {
        float v = x[i];
        s += v; s2 += v * v;
    }
    __shared__ float rs[8], rs2[8];
    float ws = warp_sum(s), ws2 = warp_sum(s2);
    int wid = tid >> 5, lane = tid & 31;
    if (lane == 0) { rs[wid] = ws; rs2[wid] = ws2; }
    __syncthreads();
    float ts = 0.f, ts2 = 0.f;
    #pragma unroll
    for (int i = 0; i < 8; i++) { ts += rs[i]; ts2 += rs2[i]; }
    float mean = ts * (1.0f / DM);
    float var  = ts2 * (1.0f / DM) - mean * mean;
    float inv  = rsqrtf(var + LN_EPS);
    for (int i = tid; i < DM; i += 256)
        y[i] = (x[i] - mean) * inv * w[i] + b[i];
}

// ---------------- RoPE ----------------
__global__ void rope_kernel(float* __restrict__ q, float* __restrict__ k,
                            const int* __restrict__ pos_ids) {
    int idx = blockIdx.x * blockDim.x + threadIdx.x;
    int j = idx & 7;
    int h = (idx >> 3) & 31;
    int l = idx >> 8;
    if (l >= LL) return;
    int pos = pos_ids[l & (SQ - 1)];
    float inv_freq = __expf(-(float)j * 1.1512925464970230f);
    float ang = (float)pos * inv_freq;
    float c = cosf(ang), s = sinf(ang);
    size_t base = (size_t)l * DM + h * HDM;
    float q1 = q[base + j], q2 = q[base + j + 8];
    q[base + j]     = q1 * c - q2 * s;
    q[base + j + 8] = q2 * c + q1 * s;
    float k1 = k[base + j], k2 = k[base + j + 8];
    k[base + j]     = k1 * c - k2 * s;
    k[base + j + 8] = k2 * c + k1 * s;
}

// ---------------- Attention (structured mask) ----------------
__global__ void __launch_bounds__(256)
attn_kernel(const float* __restrict__ q, const float* __restrict__ k,
            const float* __restrict__ v, float* __restrict__ out) {
    int h = blockIdx.y;
    int tid = threadIdx.x;
    int warp = tid >> 5, lane = tid & 31;
    int i = blockIdx.x * 8 + warp;

    __shared__ float qs[8][HDM];
    __shared__ float ks[32][HDM + 1];
    __shared__ float vs[32][HDM + 2];

    for (int idx = tid; idx < 8 * HDM; idx += 256) {
        int r = idx >> 6, c = idx & 63;
        qs[r][c] = q[(size_t)(SQ + blockIdx.x * 8 + r) * DM + h * HDM + c];
    }
    __syncthreads();

    float m = -INFINITY, lsum = 0.f, acc0 = 0.f, acc1 = 0.f;
    int i_max = blockIdx.x * 8 + 7;
    int nchk = (i_max + 31) >> 5;
    for (int ch = 0; ch < nchk; ch++) {
        int j0 = ch << 5;
        __syncthreads();
        for (int idx = tid; idx < 32 * HDM; idx += 256) {
            int r = idx >> 6, c = idx & 63;
            size_t off = (size_t)(j0 + r) * DM + h * HDM + c;
            ks[r][c] = k[off];
            vs[r][c] = v[off];
        }
        __syncthreads();
        if (j0 < i) {
            int j = j0 + lane;
            float s_t = 0.f;
            #pragma unroll
            for (int d = 0; d < HDM; d++) s_t += qs[warp][d] * ks[lane][d];
            s_t *= 0.125f;
            if (j >= i) s_t = -INFINITY;
            float mx = warp_max(s_t);
            float m_new = fmaxf(m, mx);
            float scale = __expf(m - m_new);
            float p = __expf(s_t - m_new);
            lsum = lsum * scale + warp_sum(p);
            acc0 *= scale; acc1 *= scale;
            #pragma unroll
            for (int t = 0; t < 32; t++) {
                float pt = __shfl_sync(0xffffffffu, p, t);
                acc0 += pt * vs[t][2 * lane];
                acc1 += pt * vs[t][2 * lane + 1];
            }
            m = m_new;
        }
    }
    {
        const float* kself = k + (size_t)(SQ + i) * DM + h * HDM;
        const float* vself = v + (size_t)(SQ + i) * DM + h * HDM;
        float part = qs[warp][2 * lane] * kself[2 * lane]
                   + qs[warp][2 * lane + 1] * kself[2 * lane + 1];
        float s_self = warp_sum(part) * 0.125f;
        float m_new = fmaxf(m, s_self);
        float scale = __expf(m - m_new);
        float pself = __expf(s_self - m_new);
        lsum = lsum * scale + pself;
        acc0 = acc0 * scale + pself * vself[2 * lane];
        acc1 = acc1 * scale + pself * vself[2 * lane + 1];
    }
    float invl = 1.0f / lsum;
    size_t ob = (size_t)i * DM + h * HDM;
    out[ob + 2 * lane]     = acc0 * invl;
    out[ob + 2 * lane + 1] = acc1 * invl;
}

// ---------------- SiLU(gate)*up ----------------
__global__ void silu_mul_kernel(float* __restrict__ gate, const float* __restrict__ up) {
    size_t i = (size_t)blockIdx.x * blockDim.x + threadIdx.x;
    if (i < (size_t)SQ * FFD) {
        float g = gate[i];
        gate[i] = g / (1.0f + __expf(-g)) * up[i];
    }
}

// ---------------- launch ----------------
static inline void split(const float* in, __nv_bfloat16* hi, __nv_bfloat16* lo, size_t n) {
    int n4 = (int)(n / 4);
    split_kernel<<<(n4 + 255) / 256, 256>>>(in, hi, lo, n4);
}

extern "C" void kernel_launch(void* const* d_in, const int* in_sizes, int n_in,
                              void* d_out, int out_size) {
    const float* hidden = (const float*)d_in[0];
    const float* memory = (const float*)d_in[1];
    const int*   pos    = (const int*)d_in[3];
    const float* ln1w   = (const float*)d_in[4];
    const float* ln1b   = (const float*)d_in[5];
    const float* ln2w   = (const float*)d_in[6];
    const float* ln2b   = (const float*)d_in[7];
    const float* Wq     = (const float*)d_in[8];
    const float* Wk     = (const float*)d_in[9];
    const float* Wv     = (const float*)d_in[10];
    const float* Wo     = (const float*)d_in[11];
    const float* Wg     = (const float*)d_in[12];
    const float* Wu     = (const float*)d_in[13];
    const float* Wd     = (const float*)d_in[14];
    float* out = (float*)d_out;

    float *x, *q, *k, *v, *attn, *h, *h2, *gate, *up;
    cudaGetSymbolAddress((void**)&x, g_x);       cudaGetSymbolAddress((void**)&q, g_q);
    cudaGetSymbolAddress((void**)&k, g_k);       cudaGetSymbolAddress((void**)&v, g_v);
    cudaGetSymbolAddress((void**)&attn, g_attn); cudaGetSymbolAddress((void**)&h, g_h);
    cudaGetSymbolAddress((void**)&h2, g_h2);     cudaGetSymbolAddress((void**)&gate, g_gate);
    cudaGetSymbolAddress((void**)&up, g_up);

    __nv_bfloat16 *xh, *xl, *ath, *atl, *h2h, *h2l, *gth, *gtl;
    __nv_bfloat16 *wqh, *wql, *wkh, *wkl, *wvh, *wvl, *woh, *wol;
    __nv_bfloat16 *wgh, *wgl, *wuh, *wul, *wdh, *wdl;
    cudaGetSymbolAddress((void**)&xh, g_xh);   cudaGetSymbolAddress((void**)&xl, g_xl);
    cudaGetSymbolAddress((void**)&ath, g_ath); cudaGetSymbolAddress((void**)&atl, g_atl);
    cudaGetSymbolAddress((void**)&h2h, g_h2h); cudaGetSymbolAddress((void**)&h2l, g_h2l);
    cudaGetSymbolAddress((void**)&gth, g_gth); cudaGetSymbolAddress((void**)&gtl, g_gtl);
    cudaGetSymbolAddress((void**)&wqh, g_wqh); cudaGetSymbolAddress((void**)&wql, g_wql);
    cudaGetSymbolAddress((void**)&wkh, g_wkh); cudaGetSymbolAddress((void**)&wkl, g_wkl);
    cudaGetSymbolAddress((void**)&wvh, g_wvh); cudaGetSymbolAddress((void**)&wvl, g_wvl);
    cudaGetSymbolAddress((void**)&woh, g_woh); cudaGetSymbolAddress((void**)&wol, g_wol);
    cudaGetSymbolAddress((void**)&wgh, g_wgh); cudaGetSymbolAddress((void**)&wgl, g_wgl);
    cudaGetSymbolAddress((void**)&wuh, g_wuh); cudaGetSymbolAddress((void**)&wul, g_wul);
    cudaGetSymbolAddress((void**)&wdh, g_wdh); cudaGetSymbolAddress((void**)&wdl, g_wdl);

    cudaFuncSetAttribute(gemm_hmma, cudaFuncAttributeMaxDynamicSharedMemorySize, SMEM_BYTES);

    // weight splits
    split(Wq, wqh, wql, (size_t)DM * DM);
    split(Wk, wkh, wkl, (size_t)DM * DM);
    split(Wv, wvh, wvl, (size_t)DM * DM);
    split(Wo, woh, wol, (size_t)DM * DM);
    split(Wg, wgh, wgl, (size_t)FFD * DM);
    split(Wu, wuh, wul, (size_t)FFD * DM);
    split(Wd, wdh, wdl, (size_t)DM * FFD);

    // LN1 -> x, split
    ln_kernel<<<SQ, 256>>>(memory, x, ln1w, ln1b);
    ln_kernel<<<SQ, 256>>>(hidden, x + (size_t)SQ * DM, ln1w, ln1b);
    split(x, xh, xl, (size_t)LL * DM);

    // QKV
    dim3 gq(DM / BNH, LL / BMH);
    gemm_hmma<<<gq, 256, SMEM_BYTES>>>(xh, xl, wqh, wql, nullptr, q, LL, DM, DM);
    gemm_hmma<<<gq, 256, SMEM_BYTES>>>(xh, xl, wkh, wkl, nullptr, k, LL, DM, DM);
    gemm_hmma<<<gq, 256, SMEM_BYTES>>>(xh, xl, wvh, wvl, nullptr, v, LL, DM, DM);

    rope_kernel<<<(LL * NH * 8) / 256, 256>>>(q, k, pos);
    attn_kernel<<<dim3(SQ / 8, NH), 256>>>(q, k, v, attn);

    // Wo + residual
    split(attn, ath, atl, (size_t)SQ * DM);
    gemm_hmma<<<dim3(DM / BNH, SQ / BMH), 256, SMEM_BYTES>>>(ath, atl, woh, wol, hidden, h, SQ, DM, DM);

    // LN2 + MLP
    ln_kernel<<<SQ, 256>>>(h, h2, ln2w, ln2b);
    split(h2, h2h, h2l, (size_t)SQ * DM);
    dim3 gff(FFD / BNH, SQ / BMH);
    gemm_hmma<<<gff, 256, SMEM_BYTES>>>(h2h, h2l, wgh, wgl, nullptr, gate, SQ, FFD, DM);
    gemm_hmma<<<gff, 256, SMEM_BYTES>>>(h2h, h2l, wuh, wul, nullptr, up, SQ, FFD, DM);
    silu_mul_kernel<<<(SQ * FFD) / 256, 256>>>(gate, up);
    split(gate, gth, gtl, (size_t)SQ * FFD);

    gemm_hmma<<<dim3(DM / BNH, SQ / BMH), 256, SMEM_BYTES>>>(gth, gtl, wdh, wdl, h, out, SQ, DM, FFD);
}